// round 8
// baseline (speedup 1.0000x reference)
#include <cuda_runtime.h>
#include <math.h>

#define Bb 4
#define Nn 2048
#define Dd 1024
#define Hh 16
#define dhh 64
#define Ff 2048
#define PADn 8192
#define FBn 4097
#define NCn 32
#define PI_D 3.14159265358979323846

__device__ float  g_qkvg[(size_t)Bb * Nn * 4 * Dd];
__device__ float  g_phiq[(size_t)Bb * Hh * Nn * dhh];
__device__ float  g_write[(size_t)Bb * Hh * Nn * 2 * dhh];
__device__ float  g_ctrl[Bb * Hh * NCn];
__device__ float2 g_mod[(size_t)Bb * Hh * FBn];
__device__ float  g_conv[(size_t)Bb * Hh * Ff * 2 * dhh];
__device__ float  g_att[(size_t)Bb * Nn * Dd];
__device__ float2 g_twid[PADn / 2];      // fp32 correctly-rounded twiddles
__device__ double2 g_dtwid[PADn / 2];    // double twiddles for kern FFT
__device__ float2 g_basefft[Hh * FBn];   // fp32 kern spectrum (exact-double FFT)

__device__ __forceinline__ float2 cmulf(float2 a, float2 b) {
    return make_float2(a.x * b.x - a.y * b.y, a.x * b.y + a.y * b.x);
}
// XLA logistic expansion: sigmoid(x) = 0.5*tanh(0.5x) + 0.5 (uncontracted)
__device__ __forceinline__ float xla_sigmoid(float x) {
    return __fadd_rn(__fmul_rn(0.5f, tanhf(__fmul_rn(0.5f, x))), 0.5f);
}

// ---------------- twiddle tables ----------------
__global__ void twid_kernel() {
    int j = blockIdx.x * 256 + threadIdx.x;
    if (j < PADn / 2) {
        double th = -2.0 * PI_D * (double)j / (double)PADn;
        g_twid[j] = make_float2((float)cos(th), (float)sin(th));
        g_dtwid[j] = make_double2(cos(th), sin(th));
    }
}

// ---------------- faithful fp32 kern -> double FFT -> fp32 spectrum ----------------
__global__ void __launch_bounds__(512) kernfft_kernel(const float* __restrict__ wave_freq,
                                                      const float* __restrict__ wave_damp,
                                                      const float* __restrict__ wave_phase) {
    extern __shared__ double sd[];
    double* re = sd;
    double* im = sd + PADn;
    int h = blockIdx.x;
    int tid = threadIdx.x;
    float af = (float)exp((double)wave_damp[h]);
    float fr = wave_freq[h];
    float ph = wave_phase[h];

    for (int t = tid; t < PADn; t += 512) {
        float kv = 0.f;
        if (t < Ff) {
            float tf = (float)t / 2048.0f;
            float m1 = __fmul_rn(-af, tf);
            float e1 = (float)exp((double)m1);
            float arg = __fadd_rn(__fmul_rn(fr, tf), ph);
            float c1 = (float)cos((double)arg);
            kv = __fmul_rn(e1, c1);
        }
        int rv = __brev((unsigned)t) >> 19;
        re[rv] = (double)kv;
        im[rv] = 0.0;
    }
    __syncthreads();
#pragma unroll 1
    for (int s = 1; s <= 13; s++) {
        int half = 1 << (s - 1), shift = 13 - s;
        for (int idx = tid; idx < 4096; idx += 512) {
            int pos = idx & (half - 1);
            int base = ((idx >> (s - 1)) << s) + pos;
            double2 wv = g_dtwid[pos << shift];
            double ar = re[base], ai = im[base];
            double br = re[base + half], bi = im[base + half];
            double tr = br * wv.x - bi * wv.y;
            double ti = br * wv.y + bi * wv.x;
            re[base] = ar + tr; im[base] = ai + ti;
            re[base + half] = ar - tr; im[base + half] = ai - ti;
        }
        __syncthreads();
    }
    for (int k = tid; k < FBn; k += 512)
        g_basefft[h * FBn + k] = make_float2((float)re[k], (float)im[k]);
}

// ---------------- fp32 GEMM: C[M,Nc] = A[M,K] * Bm[Nc,K]^T + bias[Nc] ----------------
__global__ void __launch_bounds__(256) gemm_nt(const float* __restrict__ A,
                                               const float* __restrict__ Bm,
                                               const float* __restrict__ bias,
                                               float* __restrict__ C,
                                               int M, int Nc, int K) {
    __shared__ __align__(16) float As[16][132];
    __shared__ __align__(16) float Bs[16][132];
    int tid = threadIdx.x;
    int m0 = blockIdx.y * 128, n0 = blockIdx.x * 128;
    int rm = (tid >> 4) * 8, rn = (tid & 15) * 8;
    int lr = tid >> 2, lc = (tid & 3) << 2;
    float acc[8][8];
#pragma unroll
    for (int i = 0; i < 8; i++)
#pragma unroll
        for (int j = 0; j < 8; j++) acc[i][j] = 0.f;

    for (int k0 = 0; k0 < K; k0 += 16) {
        float4 a0 = *(const float4*)(A + (size_t)(m0 + lr) * K + k0 + lc);
        float4 a1 = *(const float4*)(A + (size_t)(m0 + 64 + lr) * K + k0 + lc);
        float4 b0 = *(const float4*)(Bm + (size_t)(n0 + lr) * K + k0 + lc);
        float4 b1 = *(const float4*)(Bm + (size_t)(n0 + 64 + lr) * K + k0 + lc);
        __syncthreads();
        As[lc + 0][lr] = a0.x; As[lc + 1][lr] = a0.y; As[lc + 2][lr] = a0.z; As[lc + 3][lr] = a0.w;
        As[lc + 0][64 + lr] = a1.x; As[lc + 1][64 + lr] = a1.y; As[lc + 2][64 + lr] = a1.z; As[lc + 3][64 + lr] = a1.w;
        Bs[lc + 0][lr] = b0.x; Bs[lc + 1][lr] = b0.y; Bs[lc + 2][lr] = b0.z; Bs[lc + 3][lr] = b0.w;
        Bs[lc + 0][64 + lr] = b1.x; Bs[lc + 1][64 + lr] = b1.y; Bs[lc + 2][64 + lr] = b1.z; Bs[lc + 3][64 + lr] = b1.w;
        __syncthreads();
#pragma unroll
        for (int kk = 0; kk < 16; kk++) {
            float4 av0 = *(const float4*)&As[kk][rm];
            float4 av1 = *(const float4*)&As[kk][rm + 4];
            float4 bv0 = *(const float4*)&Bs[kk][rn];
            float4 bv1 = *(const float4*)&Bs[kk][rn + 4];
            float av[8] = {av0.x, av0.y, av0.z, av0.w, av1.x, av1.y, av1.z, av1.w};
            float bv[8] = {bv0.x, bv0.y, bv0.z, bv0.w, bv1.x, bv1.y, bv1.z, bv1.w};
#pragma unroll
            for (int i = 0; i < 8; i++)
#pragma unroll
                for (int j = 0; j < 8; j++) acc[i][j] += av[i] * bv[j];
        }
    }
#pragma unroll
    for (int i = 0; i < 8; i++) {
        size_t row = (size_t)(m0 + rm + i) * Nc + n0 + rn;
        float4 o0, o1;
        o0.x = acc[i][0] + bias[n0 + rn + 0];
        o0.y = acc[i][1] + bias[n0 + rn + 1];
        o0.z = acc[i][2] + bias[n0 + rn + 2];
        o0.w = acc[i][3] + bias[n0 + rn + 3];
        o1.x = acc[i][4] + bias[n0 + rn + 4];
        o1.y = acc[i][5] + bias[n0 + rn + 5];
        o1.z = acc[i][6] + bias[n0 + rn + 6];
        o1.w = acc[i][7] + bias[n0 + rn + 7];
        *(float4*)(C + row) = o0;
        *(float4*)(C + row + 4) = o1;
    }
}

// ---------------- featmaps + write-gate ----------------
#define FSPLIT 8
__global__ void __launch_bounds__(256) featmap_kernel(const float* __restrict__ qfm_w,
                                                      const float* __restrict__ qfm_b,
                                                      const float* __restrict__ kfm_w,
                                                      const float* __restrict__ kfm_b,
                                                      const float* __restrict__ wg_w,
                                                      const float* __restrict__ wg_b) {
    __shared__ float wt[2][4096];
    __shared__ float bs[2][64];
    __shared__ float xs[4][64];
    __shared__ float vs[4][64];
    __shared__ float t1s[4][64];
    __shared__ float wgw[64];
    __shared__ float wgb;

    int tid = threadIdx.x;
    int r = tid >> 6, j = tid & 63;
    int bh = blockIdx.x / FSPLIT, sp = blockIdx.x % FSPLIT;
    int b = bh >> 4, h = bh & 15;
    int n0 = sp * (Nn / FSPLIT);
    size_t rowbase = (size_t)b * Nn * 4096 + h * 64;

    for (int e = tid; e < 8192; e += 256) {
        int l = e >> 12, idx = e & 4095;
        wt[l][(idx & 63) * 64 + (idx >> 6)] = qfm_w[e];
    }
    if (tid < 128) bs[tid >> 6][tid & 63] = qfm_b[tid];
    __syncthreads();
    for (int it = 0; it < Nn / FSPLIT; it += 4) {
        int n = n0 + it + r;
        xs[r][j] = g_qkvg[rowbase + (size_t)n * 4096 + j];
        __syncthreads();
        float acc = bs[0][j];
#pragma unroll 16
        for (int i = 0; i < 64; i++) acc += xs[r][i] * wt[0][i * 64 + j];
        t1s[r][j] = fmaxf(acc, 0.f);
        __syncthreads();
        float acc2 = bs[1][j];
#pragma unroll 16
        for (int i = 0; i < 64; i++) acc2 += t1s[r][i] * wt[1][i * 64 + j];
        g_phiq[((size_t)bh * Nn + n) * 64 + j] = fmaxf(acc2, 0.f) + 1e-6f;
        __syncthreads();
    }
    __syncthreads();
    for (int e = tid; e < 8192; e += 256) {
        int l = e >> 12, idx = e & 4095;
        wt[l][(idx & 63) * 64 + (idx >> 6)] = kfm_w[e];
    }
    if (tid < 128) bs[tid >> 6][tid & 63] = kfm_b[tid];
    if (tid < 64) wgw[tid] = wg_w[tid];
    if (tid == 0) wgb = wg_b[0];
    __syncthreads();
    for (int it = 0; it < Nn / FSPLIT; it += 4) {
        int n = n0 + it + r;
        xs[r][j] = g_qkvg[rowbase + (size_t)n * 4096 + 1024 + j];
        vs[r][j] = g_qkvg[rowbase + (size_t)n * 4096 + 2048 + j];
        __syncthreads();
        float acc = bs[0][j];
        float wgacc = wgb;
#pragma unroll 16
        for (int i = 0; i < 64; i++) {
            acc += xs[r][i] * wt[0][i * 64 + j];
            wgacc += xs[r][i] * wgw[i];
        }
        float wgv = xla_sigmoid(wgacc);
        t1s[r][j] = fmaxf(acc, 0.f);
        __syncthreads();
        float acc2 = bs[1][j];
#pragma unroll 16
        for (int i = 0; i < 64; i++) acc2 += t1s[r][i] * wt[1][i * 64 + j];
        float phik = fmaxf(acc2, 0.f) + 1e-6f;
        float* wp = &g_write[((size_t)bh * Nn + n) * 128];
        wp[j] = wgv * phik * vs[r][j];
        wp[64 + j] = wgv * phik;
        __syncthreads();
    }
}

// ---------------- spectral gate MLP ----------------
__global__ void __launch_bounds__(256) sg_kernel(const float* __restrict__ ln_g,
                                                 const float* __restrict__ ln_b,
                                                 const float* __restrict__ sg_w1,
                                                 const float* __restrict__ sg_b1,
                                                 const float* __restrict__ sg_w2,
                                                 const float* __restrict__ sg_b2) {
    __shared__ float q0[1024];
    __shared__ float h1[1024];
    __shared__ float mu[16], rv[16];
    int b = blockIdx.x, tid = threadIdx.x;
    for (int i = tid; i < 1024; i += 256)
        q0[i] = g_qkvg[(size_t)b * Nn * 4096 + i];
    __syncthreads();
    if (tid < 16) {
        // two-pass mean/var like jnp.var
        float s = 0.f;
        for (int j = 0; j < 64; j++) s += q0[tid * 64 + j];
        float m = s / 64.f;
        float s2 = 0.f;
        for (int j = 0; j < 64; j++) {
            float dv = __fsub_rn(q0[tid * 64 + j], m);
            s2 += dv * dv;
        }
        mu[tid] = m;
        rv[tid] = 1.f / sqrtf(s2 / 64.f + 1e-5f);
    }
    __syncthreads();
    for (int i = tid; i < 1024; i += 256) {
        int h = i >> 6, j = i & 63;
        q0[i] = (q0[i] - mu[h]) * rv[h] * ln_g[j] + ln_b[j];
    }
    __syncthreads();
    for (int o = tid; o < 1024; o += 256) {
        float acc = sg_b1[o];
        const float* w = &sg_w1[(size_t)o * 1024];
        for (int i = 0; i < 1024; i++) acc += q0[i] * w[i];
        // gelu tanh-approx, JAX association: 0.044715*(x*x*x)
        float cube = __fmul_rn(0.044715f, __fmul_rn(acc, __fmul_rn(acc, acc)));
        float t = tanhf(__fmul_rn(0.7978845608028654f, __fadd_rn(acc, cube)));
        h1[o] = __fmul_rn(__fmul_rn(0.5f, acc), __fadd_rn(1.f, t));
    }
    __syncthreads();
    for (int o = tid; o < 512; o += 256) {
        float acc = sg_b2[o];
        const float* w = &sg_w2[(size_t)o * 1024];
        for (int i = 0; i < 1024; i++) acc += h1[i] * w[i];
        g_ctrl[b * 512 + o] = acc;
    }
}

// ---------------- mod = fp32(basefft) * fp32(1+gate) / 8192 ----------------
__global__ void mod_kernel() {
    int bh = blockIdx.x, h = bh & 15;
    int k = blockIdx.y * 256 + threadIdx.x;
    if (k >= FBn) return;

    const float* cp = &g_ctrl[bh * NCn];
    float ip = (float)k * 31.0f / 4096.0f;
    int il = (int)ip; if (il > 30) il = 30; if (il < 0) il = 0;
    float iw = ip - (float)il;
    float gate = cp[il] * (1.f - iw) + cp[il + 1] * iw;
    float gf = 1.f + gate;

    float2 base = g_basefft[h * FBn + k];
    float mr = __fmul_rn(base.x, gf) * (1.0f / 8192.0f);
    float mi = __fmul_rn(base.y, gf) * (1.0f / 8192.0f);
    g_mod[(size_t)bh * FBn + k] = make_float2(mr, mi);
}

// ---------------- packed-pair 8192-pt FFT convolution (R5: plain fp32) ----------------
__global__ void __launch_bounds__(512) fft_conv_kernel() {
    extern __shared__ float2 sm[];
    float2* buf = sm;          // 8192
    float2* tw = sm + PADn;    // 4096
    int tid = threadIdx.x;
    int bh = blockIdx.x >> 6;
    int pr = blockIdx.x & 63;
    int c0 = pr * 2, c1 = c0 + 1;

    for (int j = tid; j < 4096; j += 512) tw[j] = g_twid[j];
    for (int t = tid; t < PADn; t += 512) {
        float re = 0.f, im = 0.f;
        if (t < 2047) {
            const float* wr = &g_write[((size_t)bh * Nn + t) * 128];
            re = wr[c0]; im = wr[c1];
            if (t == 2046) {
                const float* w2 = &g_write[((size_t)bh * Nn + 2047) * 128];
                re += w2[c0]; im += w2[c1];
            }
        }
        buf[__brev((unsigned)t) >> 19] = make_float2(re, im);
    }
    __syncthreads();
#pragma unroll 1
    for (int s = 1; s <= 13; s++) {
        int half = 1 << (s - 1), shift = 13 - s;
        for (int idx = tid; idx < 4096; idx += 512) {
            int pos = idx & (half - 1);
            int base = ((idx >> (s - 1)) << s) + pos;
            float2 wv = tw[pos << shift];
            float2 av = buf[base], bv = buf[base + half];
            float2 bt = cmulf(bv, wv);
            buf[base] = make_float2(av.x + bt.x, av.y + bt.y);
            buf[base + half] = make_float2(av.x - bt.x, av.y - bt.y);
        }
        __syncthreads();
    }
    const float2* modp = &g_mod[(size_t)bh * FBn];
    for (int k = tid; k < PADn; k += 512) {
        float2 m = (k <= 4096) ? modp[k] : modp[PADn - k];
        if (k > 4096) m.y = -m.y;
        buf[k] = cmulf(buf[k], m);
    }
    __syncthreads();
#pragma unroll 1
    for (int s = 13; s >= 1; s--) {
        int half = 1 << (s - 1), shift = 13 - s;
        for (int idx = tid; idx < 4096; idx += 512) {
            int pos = idx & (half - 1);
            int base = ((idx >> (s - 1)) << s) + pos;
            float2 wv = tw[pos << shift];
            wv.y = -wv.y;
            float2 av = buf[base], bv = buf[base + half];
            buf[base] = make_float2(av.x + bv.x, av.y + bv.y);
            float2 dv = make_float2(av.x - bv.x, av.y - bv.y);
            buf[base + half] = cmulf(dv, wv);
        }
        __syncthreads();
    }
    for (int t = tid; t < Ff; t += 512) {
        float2 v = buf[__brev((unsigned)t) >> 19];
        float* cp = &g_conv[((size_t)bh * Ff + t) * 128];
        cp[c0] = v.x;
        cp[c1] = v.y;
    }
}

// ---------------- head coupling + gather + normalize + gate ----------------
__global__ void __launch_bounds__(128) mix_kernel(const float* __restrict__ coupling) {
    __shared__ float convs[16 * 128];
    __shared__ float ys[16 * 128];
    __shared__ float coup[256];
    __shared__ float phiq[1024];
    __shared__ float den[16];
    int tid = threadIdx.x;
    int b = blockIdx.x >> 11, n = blockIdx.x & 2047;
    int fn = n < 2046 ? n : 2046;

    for (int i = tid; i < 2048; i += 128) {
        int g = i >> 7, c = i & 127;
        convs[i] = g_conv[(((size_t)(b * Hh + g)) * Ff + fn) * 128 + c];
    }
    coup[tid] = coupling[tid];
    coup[128 + tid] = coupling[128 + tid];
    for (int i = tid; i < 1024; i += 128) {
        int h = i >> 6, j = i & 63;
        phiq[i] = g_phiq[(((size_t)(b * Hh + h)) * Nn + n) * 64 + j];
    }
    __syncthreads();
    for (int i = tid; i < 2048; i += 128) {
        int h = i >> 7, c = i & 127;
        float acc = 0.f;
#pragma unroll
        for (int g = 0; g < 16; g++) acc += coup[h * 16 + g] * convs[g * 128 + c];
        ys[i] = acc;
    }
    __syncthreads();
    // den: XLA-style warp row-reduction in fp32.
    // lane term = p[lane]*y[lane] + p[lane+32]*y[lane+32] (add of two muls),
    // then 5-level binary shuffle tree.
    int warp = tid >> 5, lane = tid & 31;
    for (int h = warp; h < 16; h += 4) {
        float t1 = __fmul_rn(phiq[h * 64 + lane], ys[h * 128 + 64 + lane]);
        float t2 = __fmul_rn(phiq[h * 64 + 32 + lane], ys[h * 128 + 96 + lane]);
        float pv = __fadd_rn(t1, t2);
#pragma unroll
        for (int o = 16; o; o >>= 1)
            pv = __fadd_rn(pv, __shfl_down_sync(0xffffffffu, pv, o));
        pv = __shfl_sync(0xffffffffu, pv, 0);
        if (lane == 0) den[h] = __fadd_rn(fabsf(pv), 1e-4f);
    }
    __syncthreads();
    const float* grow = &g_qkvg[((size_t)b * Nn + n) * 4096 + 3072];
    float* arow = &g_att[((size_t)b * Nn + n) * 1024];
    for (int i = tid; i < 1024; i += 128) {
        int h = i >> 6;
        float sg = xla_sigmoid(grow[i]);
        arow[i] = phiq[i] * ys[h * 128 + (i & 63)] / den[h] * sg;
    }
}

// ---------------- launcher ----------------
extern "C" void kernel_launch(void* const* d_in, const int* in_sizes, int n_in,
                              void* d_out, int out_size) {
    const float* x       = (const float*)d_in[0];
    const float* w_qkvg  = (const float*)d_in[1];
    const float* b_qkvg  = (const float*)d_in[2];
    const float* w_out   = (const float*)d_in[3];
    const float* b_out   = (const float*)d_in[4];
    const float* qfm_w   = (const float*)d_in[5];
    const float* qfm_b   = (const float*)d_in[6];
    const float* kfm_w   = (const float*)d_in[7];
    const float* kfm_b   = (const float*)d_in[8];
    const float* wg_w    = (const float*)d_in[9];
    const float* wg_b    = (const float*)d_in[10];
    const float* ln_g    = (const float*)d_in[11];
    const float* ln_b    = (const float*)d_in[12];
    const float* sg_w1   = (const float*)d_in[13];
    const float* sg_b1   = (const float*)d_in[14];
    const float* sg_w2   = (const float*)d_in[15];
    const float* sg_b2   = (const float*)d_in[16];
    const float* wfreq   = (const float*)d_in[17];
    const float* wdamp   = (const float*)d_in[18];
    const float* wphase  = (const float*)d_in[19];
    const float* coupling= (const float*)d_in[20];
    (void)in_sizes; (void)n_in; (void)out_size;

    void* p;
    cudaGetSymbolAddress(&p, g_qkvg); float* qkvg = (float*)p;
    cudaGetSymbolAddress(&p, g_att);  float* att  = (float*)p;

    twid_kernel<<<16, 256>>>();
    gemm_nt<<<dim3(4096 / 128, 8192 / 128), 256>>>(x, w_qkvg, b_qkvg, qkvg, 8192, 4096, 1024);
    cudaFuncSetAttribute(kernfft_kernel, cudaFuncAttributeMaxDynamicSharedMemorySize, 131072);
    kernfft_kernel<<<Hh, 512, 131072>>>(wfreq, wdamp, wphase);
    featmap_kernel<<<Bb * Hh * FSPLIT, 256>>>(qfm_w, qfm_b, kfm_w, kfm_b, wg_w, wg_b);
    sg_kernel<<<Bb, 256>>>(ln_g, ln_b, sg_w1, sg_b1, sg_w2, sg_b2);
    mod_kernel<<<dim3(Bb * Hh, (FBn + 255) / 256), 256>>>();
    cudaFuncSetAttribute(fft_conv_kernel, cudaFuncAttributeMaxDynamicSharedMemorySize, 98304);
    fft_conv_kernel<<<Bb * Hh * 64, 512, 98304>>>();
    mix_kernel<<<Bb * Nn, 128>>>(coupling);
    gemm_nt<<<dim3(1024 / 128, 8192 / 128), 256>>>(att, w_out, b_out, (float*)d_out, 8192, 1024, 1024);
}